// round 1
// baseline (speedup 1.0000x reference)
#include <cuda_runtime.h>

// Problem constants
#define NJ   14      // joints
#define NDP  3       // point dim
#define NC   128     // c channels
#define CIN  131     // C + D
#define NH   128     // hidden
#define NB   2
#define NT   32768
#define TILE 128     // t-points per CTA
#define AS   132     // activation smem row stride (floats), 16B-aligned
#define WS   136     // weight-chunk smem row stride (floats), 16B-aligned
#define NTHREADS 256

// smem layout (floats): xs[CIN*AS] | hA[NH*AS] | hB[NH*AS] | ws[32*WS]
#define XS_F (CIN * AS)
#define H_F  (NH * AS)
#define WS_F (32 * WS)
#define SMEM_FLOATS (XS_F + 2 * H_F + WS_F)
#define SMEM_BYTES  (SMEM_FLOATS * sizeof(float))

// One k-step of the 128x128 register-tiled GEMM: 8x8 outer product.
__device__ __forceinline__ void kstep(const float* __restrict__ wrow,
                                      const float* __restrict__ irow,
                                      float acc[8][8]) {
    float4 a0 = *(const float4*)(wrow);
    float4 a1 = *(const float4*)(wrow + 4);
    float4 b0 = *(const float4*)(irow);
    float4 b1 = *(const float4*)(irow + 4);
    float a[8] = {a0.x, a0.y, a0.z, a0.w, a1.x, a1.y, a1.z, a1.w};
    float b[8] = {b0.x, b0.y, b0.z, b0.w, b1.x, b1.y, b1.z, b1.w};
#pragma unroll
    for (int i = 0; i < 8; i++)
#pragma unroll
        for (int n = 0; n < 8; n++)
            acc[i][n] = fmaf(a[i], b[n], acc[i][n]);
}

// out_s[m][n] = relu( sum_k Wg[m][k] * in_s[k][n] + bg[m] ),  m,n in [0,128)
// Wg: global, row-major [128][K]. in_s/out_s: smem [K/128][AS]. ws: smem W chunk.
__device__ __forceinline__ void gemm_relu(const float* __restrict__ Wg,
                                          const float* __restrict__ bg,
                                          int K,
                                          const float* __restrict__ in_s,
                                          float* __restrict__ out_s,
                                          float* __restrict__ ws,
                                          int tid, int m_base, int n_base) {
    float acc[8][8];
#pragma unroll
    for (int i = 0; i < 8; i++)
#pragma unroll
        for (int n = 0; n < 8; n++) acc[i][n] = 0.f;

    for (int k0 = 0; k0 < K; k0 += 32) {
        const int kc = min(32, K - k0);
        __syncthreads();
        // stage W chunk: ws[kk][m] = Wg[m*K + k0 + kk]  (coalesced along kk)
        if (kc == 32) {
            for (int idx = tid; idx < 32 * NH; idx += NTHREADS) {
                int m = idx >> 5, kk = idx & 31;
                ws[kk * WS + m] = Wg[m * K + k0 + kk];
            }
        } else {
            for (int idx = tid; idx < kc * NH; idx += NTHREADS) {
                int m = idx / kc, kk = idx - m * kc;
                ws[kk * WS + m] = Wg[m * K + k0 + kk];
            }
        }
        __syncthreads();

        const float* ip = in_s + k0 * AS + n_base;
        if (kc == 32) {
#pragma unroll 8
            for (int kk = 0; kk < 32; kk++)
                kstep(ws + kk * WS + m_base, ip + kk * AS, acc);
        } else {
            for (int kk = 0; kk < kc; kk++)
                kstep(ws + kk * WS + m_base, ip + kk * AS, acc);
        }
    }

    // epilogue: bias + relu, write to out_s
#pragma unroll
    for (int i = 0; i < 8; i++) {
        float bias = __ldg(bg + m_base + i);
#pragma unroll
        for (int n = 0; n < 8; n++) {
            float v = acc[i][n] + bias;
            out_s[(m_base + i) * AS + n_base + n] = fmaxf(v, 0.f);
        }
    }
}

__global__ __launch_bounds__(NTHREADS, 1)
void ptf_kernel(const float* __restrict__ p,
                const float* __restrict__ c,
                const float* __restrict__ ps,
                const float* __restrict__ W0, const float* __restrict__ b0,
                const float* __restrict__ W1, const float* __restrict__ b1,
                const float* __restrict__ W2, const float* __restrict__ b2,
                const float* __restrict__ W3, const float* __restrict__ b3,
                float* __restrict__ out) {
    extern __shared__ float sm[];
    float* xs = sm;                 // [CIN][AS]   layer0 input (rows 0..2 = p, 3..130 = c)
    float* hA = xs + XS_F;          // [NH][AS]
    float* hB = hA + H_F;           // [NH][AS]
    float* ws = hB + H_F;           // [32][WS]  weight chunk / reduction scratch

    const int tid = threadIdx.x;
    const int t0  = blockIdx.x * TILE;
    const int b   = blockIdx.y;
    const int j0  = blockIdx.z * 7;   // joints [j0, j0+7)

    // Load the c part of the layer-0 input once (shared across joints).
    {
        const float* cb = c + (size_t)b * NC * NT + t0;
        for (int idx = tid; idx < NC * TILE; idx += NTHREADS) {
            int row = idx >> 7, col = idx & 127;
            xs[(NDP + row) * AS + col] = cb[(size_t)row * NT + col];
        }
    }

    const int m_base = (tid >> 4) << 3;
    const int n_base = (tid & 15) << 3;
    const int n3     = tid & 127;      // layer-3 column
    const int half   = tid >> 7;       // layer-3 h-half

    float out_val = 0.f;

    for (int jj = 0; jj < 7; jj++) {
        const int j = j0 + jj;
        // p rows for this joint
        for (int idx = tid; idx < NDP * TILE; idx += NTHREADS) {
            int row = idx >> 7, col = idx & 127;
            xs[row * AS + col] =
                p[((size_t)b * NJ * NDP + (size_t)j * NDP + row) * NT + t0 + col];
        }
        // (gemm's leading __syncthreads orders the writes above)
        gemm_relu(W0 + (size_t)j * NH * CIN, b0 + j * NH, CIN, xs, hA, ws, tid, m_base, n_base);
        gemm_relu(W1 + (size_t)j * NH * NH,  b1 + j * NH, NH,  hA, hB, ws, tid, m_base, n_base);
        gemm_relu(W2 + (size_t)j * NH * NH,  b2 + j * NH, NH,  hB, hA, ws, tid, m_base, n_base);
        __syncthreads();

        // layer 3: o[n] = sum_h W3[j][h] * hA[h][n] + b3[j]; split h over 2 halves
        {
            const float* w3 = W3 + (size_t)j * NH;
            const float* col = hA + n3;
            float part = 0.f;
            const int h0 = half * 64;
#pragma unroll 16
            for (int h = h0; h < h0 + 64; h++)
                part = fmaf(__ldg(w3 + h), col[(size_t)h * AS], part);
            ws[tid] = part;
            __syncthreads();
            if (tid < 128) {
                float o = ws[tid] + ws[tid + 128] + __ldg(b3 + j);
                out_val = fmaf(o, __ldg(ps + ((size_t)b * NJ + j) * NT + t0 + n3), out_val);
            }
            __syncthreads();
        }
    }

    if (tid < 128)
        atomicAdd(&out[(size_t)b * NT + t0 + n3], out_val * (1.0f / 14.0f));
}

extern "C" void kernel_launch(void* const* d_in, const int* in_sizes, int n_in,
                              void* d_out, int out_size) {
    (void)in_sizes; (void)n_in;
    const float* p  = (const float*)d_in[0];
    // d_in[1] = z, unused by the reference computation
    const float* c  = (const float*)d_in[2];
    const float* ps = (const float*)d_in[3];
    const float* W0 = (const float*)d_in[4];
    const float* b0 = (const float*)d_in[5];
    const float* W1 = (const float*)d_in[6];
    const float* b1 = (const float*)d_in[7];
    const float* W2 = (const float*)d_in[8];
    const float* b2 = (const float*)d_in[9];
    const float* W3 = (const float*)d_in[10];
    const float* b3 = (const float*)d_in[11];
    float* out = (float*)d_out;

    cudaMemsetAsync(out, 0, (size_t)out_size * sizeof(float));

    cudaFuncSetAttribute(ptf_kernel, cudaFuncAttributeMaxDynamicSharedMemorySize,
                         (int)SMEM_BYTES);

    dim3 grid(NT / TILE, NB, 2);   // 256 x 2 x 2 = 1024 CTAs
    ptf_kernel<<<grid, NTHREADS, SMEM_BYTES>>>(p, c, ps, W0, b0, W1, b1, W2, b2,
                                               W3, b3, out);
}

// round 4
// speedup vs baseline: 4.9572x; 4.9572x over previous
#include <cuda_runtime.h>
#include <cuda_fp16.h>
#include <cstdint>

#define NJ 14
#define NB 2
#define NT 32768
#define NH 128
#define CIN 131

// smem (bytes): AH[128][68]u32 @0 | AL @34816 | W @69632 | bias 3*128f @104448
// | w0p 3*128f @105984 | w3 128f @107520 | scr 128f @108032
#define RS 68            // row stride in u32 (272 B) -> ldmatrix conflict-free
#define SM_AH 0
#define SM_AL 34816
#define SM_WB 69632
#define SMEM_BYTES 108544

__device__ uint32_t g_w16[NJ * 3 * 8192];   // fp16x2 weights [j][layer][h_out(128)][kw(64)]

// ---------- helpers ----------
__device__ __forceinline__ uint32_t smem_u32(const void* p) {
    uint32_t a;
    asm("{ .reg .u64 t; cvta.to.shared.u64 t, %1; cvt.u32.u64 %0, t; }" : "=r"(a) : "l"(p));
    return a;
}
__device__ __forceinline__ void ldsm4(uint32_t* r, uint32_t addr) {
    asm volatile("ldmatrix.sync.aligned.m8n8.x4.shared.b16 {%0,%1,%2,%3}, [%4];"
                 : "=r"(r[0]), "=r"(r[1]), "=r"(r[2]), "=r"(r[3]) : "r"(addr));
}
__device__ __forceinline__ void mma16816(float* d, const uint32_t* a,
                                         uint32_t b0, uint32_t b1) {
    asm volatile(
        "mma.sync.aligned.m16n8k16.row.col.f32.f16.f16.f32 "
        "{%0,%1,%2,%3}, {%4,%5,%6,%7}, {%8,%9}, {%0,%1,%2,%3};"
        : "+f"(d[0]), "+f"(d[1]), "+f"(d[2]), "+f"(d[3])
        : "r"(a[0]), "r"(a[1]), "r"(a[2]), "r"(a[3]), "r"(b0), "r"(b1));
}
__device__ __forceinline__ void cpasync16(uint32_t dst, const void* src) {
    asm volatile("cp.async.ca.shared.global [%0], [%1], 16;" :: "r"(dst), "l"(src));
}
#define CP_COMMIT() asm volatile("cp.async.commit_group;" ::: "memory")
#define CP_WAIT0()  asm volatile("cp.async.wait_group 0;" ::: "memory")

__device__ __forceinline__ uint32_t h2bits(half2 h) {
    return *reinterpret_cast<uint32_t*>(&h);
}

// ---------- weight pre-conversion (fp32 -> fp16 pairs along k) ----------
__global__ void convert_weights(const float* __restrict__ W0,
                                const float* __restrict__ W1,
                                const float* __restrict__ W2) {
    int j = blockIdx.x, l = blockIdx.y;
    const float* W = (l == 0) ? W0 : ((l == 1) ? W1 : W2);
    int K = (l == 0) ? CIN : NH;
    int koff = (l == 0) ? 3 : 0;
    uint32_t* dst = g_w16 + (size_t)(j * 3 + l) * 8192;
    for (int i = threadIdx.x; i < 8192; i += blockDim.x) {
        int h = i >> 6, kw = i & 63;
        const float* row = W + ((size_t)j * NH + h) * K + koff;
        half2 pk = __floats2half2_rn(row[2 * kw], row[2 * kw + 1]);
        dst[i] = h2bits(pk);
    }
}

// ---------- main kernel ----------
__global__ __launch_bounds__(256, 2)
void ptf_hmma(const float* __restrict__ p,
              const float* __restrict__ c,
              const float* __restrict__ ps,
              const float* __restrict__ W0g,
              const float* __restrict__ b0g,
              const float* __restrict__ b1g,
              const float* __restrict__ b2g,
              const float* __restrict__ W3g,
              const float* __restrict__ b3g,
              float* __restrict__ out) {
    extern __shared__ uint32_t sm[];
    uint32_t* AH = sm;                    // [128][RS]
    uint32_t* AL = sm + 128 * RS;
    float* bias_s = (float*)(sm + 3 * 128 * RS);  // [3][128]
    float* w0p_s  = bias_s + 384;                 // [3][128]
    float* w3_s   = w0p_s + 384;                  // [128]
    float* scr    = w3_s + 128;                   // [128]

    const int tid = threadIdx.x, lane = tid & 31, wid = tid >> 5;
    const int mb = (wid & 3) * 32;        // t-rows of this warp
    const int nb = (wid >> 2) * 64;       // h-cols of this warp
    const int t0 = blockIdx.x * 128, b = blockIdx.y, j = blockIdx.z;

    const uint32_t sbase = smem_u32(sm);
    // ldmatrix lane address components
    const int arow_l = (lane & 7) + ((lane >> 3) & 1) * 8;  // A: rows, +8 for lanes 8-15
    const int akoff  = ((lane >> 4) & 1) * 16;              // A: +16B for lanes 16-31
    const int brow_l = (lane & 7) + ((lane >> 4) & 1) * 8;  // B: rows, +8 for lanes 16-31
    const int bkoff  = ((lane >> 3) & 1) * 16;              // B: +16B for lanes 8-15

    // fold sbase into ALL ldmatrix bases (R3 bug: boff was missing sbase)
    uint32_t aoffH[2], aoffL[2];
#pragma unroll
    for (int mf = 0; mf < 2; mf++) {
        uint32_t ro = (uint32_t)((mb + mf * 16 + arow_l) * (RS * 4) + akoff);
        aoffH[mf] = sbase + SM_AH + ro;
        aoffL[mf] = sbase + SM_AL + ro;
    }
    uint32_t boff[4];
#pragma unroll
    for (int nfp = 0; nfp < 4; nfp++)
        boff[nfp] = sbase + (uint32_t)(SM_WB + (nb + nfp * 16 + brow_l) * (RS * 4) + bkoff);

    // ---- stage c -> act (split hi/lo fp16), coalesced reads ----
    {
        const float* cb = c + (size_t)b * NH * NT + t0;
#pragma unroll 4
        for (int i = tid; i < 8192; i += 256) {
            int t = i & 127, kw = i >> 7;
            float v0 = __ldg(cb + (size_t)(2 * kw) * NT + t);
            float v1 = __ldg(cb + (size_t)(2 * kw + 1) * NT + t);
            half2 hi = __floats2half2_rn(v0, v1);
            float2 hf = __half22float2(hi);
            half2 lo = __floats2half2_rn(v0 - hf.x, v1 - hf.y);
            AH[t * RS + kw] = h2bits(hi);
            AL[t * RS + kw] = h2bits(lo);
        }
    }
    // ---- stage W0 via cp.async ----
    {
        const uint32_t* src = g_w16 + (size_t)(j * 3) * 8192;
        for (int i = tid; i < 2048; i += 256)
            cpasync16(sbase + SM_WB + (i >> 4) * (RS * 4) + (i & 15) * 16, src + i * 4);
        CP_COMMIT();
    }
    if (tid < 128) {
        bias_s[tid]       = __ldg(b0g + j * NH + tid);
        bias_s[128 + tid] = __ldg(b1g + j * NH + tid);
        bias_s[256 + tid] = __ldg(b2g + j * NH + tid);
        const float* w0r = W0g + ((size_t)j * NH + tid) * CIN;
        w0p_s[tid]       = __ldg(w0r);
        w0p_s[128 + tid] = __ldg(w0r + 1);
        w0p_s[256 + tid] = __ldg(w0r + 2);
        w3_s[tid] = __ldg(W3g + j * NH + tid);
        scr[tid] = 0.f;
    }
    CP_WAIT0();
    __syncthreads();

    float acc3[4] = {0.f, 0.f, 0.f, 0.f};

    for (int l = 0; l < 3; l++) {
        float acc[2][8][4];
#pragma unroll
        for (int mf = 0; mf < 2; mf++)
#pragma unroll
            for (int nf = 0; nf < 8; nf++)
#pragma unroll
                for (int q = 0; q < 4; q++) acc[mf][nf][q] = 0.f;

        // ---- k-loop: 8 chunks of k=16 ----
#pragma unroll
        for (int kc = 0; kc < 8; kc++) {
            uint32_t ah[2][4], al[2][4];
#pragma unroll
            for (int mf = 0; mf < 2; mf++) {
                ldsm4(ah[mf], aoffH[mf] + kc * 32);
                ldsm4(al[mf], aoffL[mf] + kc * 32);
            }
#pragma unroll
            for (int nfp = 0; nfp < 4; nfp++) {
                uint32_t bw[4];
                ldsm4(bw, boff[nfp] + kc * 32);
#pragma unroll
                for (int mf = 0; mf < 2; mf++) {
                    mma16816(acc[mf][2 * nfp],     ah[mf], bw[0], bw[1]);
                    mma16816(acc[mf][2 * nfp],     al[mf], bw[0], bw[1]);
                    mma16816(acc[mf][2 * nfp + 1], ah[mf], bw[2], bw[3]);
                    mma16816(acc[mf][2 * nfp + 1], al[mf], bw[2], bw[3]);
                }
            }
        }
        __syncthreads();   // all reads of act + W done

        // prefetch next layer's weights (overlaps with epilogue)
        if (l < 2) {
            const uint32_t* src = g_w16 + (size_t)(j * 3 + l + 1) * 8192;
            for (int i = tid; i < 2048; i += 256)
                cpasync16(sbase + SM_WB + (i >> 4) * (RS * 4) + (i & 15) * 16, src + i * 4);
            CP_COMMIT();
        }

        if (l < 2) {
            // epilogue: bias (+ p rank-3 for l==0), relu, split, in-place store
            float pva[2][3], pvb[2][3];
            if (l == 0) {
#pragma unroll
                for (int mf = 0; mf < 2; mf++) {
                    int r0 = t0 + mb + mf * 16 + (lane >> 2);
#pragma unroll
                    for (int d = 0; d < 3; d++) {
                        const float* pp = p + ((size_t)b * NJ * 3 + j * 3 + d) * NT;
                        pva[mf][d] = __ldg(pp + r0);
                        pvb[mf][d] = __ldg(pp + r0 + 8);
                    }
                }
            }
#pragma unroll
            for (int mf = 0; mf < 2; mf++) {
                const int r0 = mb + mf * 16 + (lane >> 2);
#pragma unroll
                for (int nf = 0; nf < 8; nf++) {
                    const int h = nb + nf * 8 + 2 * (lane & 3);
                    float2 bb = *(const float2*)(bias_s + l * 128 + h);
                    float v0 = acc[mf][nf][0] + bb.x;
                    float v1 = acc[mf][nf][1] + bb.y;
                    float v2 = acc[mf][nf][2] + bb.x;
                    float v3 = acc[mf][nf][3] + bb.y;
                    if (l == 0) {
#pragma unroll
                        for (int d = 0; d < 3; d++) {
                            float2 w = *(const float2*)(w0p_s + d * 128 + h);
                            v0 = fmaf(pva[mf][d], w.x, v0);
                            v1 = fmaf(pva[mf][d], w.y, v1);
                            v2 = fmaf(pvb[mf][d], w.x, v2);
                            v3 = fmaf(pvb[mf][d], w.y, v3);
                        }
                    }
                    v0 = fmaxf(v0, 0.f); v1 = fmaxf(v1, 0.f);
                    v2 = fmaxf(v2, 0.f); v3 = fmaxf(v3, 0.f);
                    half2 h01 = __floats2half2_rn(v0, v1);
                    float2 f01 = __half22float2(h01);
                    half2 l01 = __floats2half2_rn(v0 - f01.x, v1 - f01.y);
                    half2 h23 = __floats2half2_rn(v2, v3);
                    float2 f23 = __half22float2(h23);
                    half2 l23 = __floats2half2_rn(v2 - f23.x, v3 - f23.y);
                    const int wcol = h >> 1;
                    AH[r0 * RS + wcol]       = h2bits(h01);
                    AL[r0 * RS + wcol]       = h2bits(l01);
                    AH[(r0 + 8) * RS + wcol] = h2bits(h23);
                    AL[(r0 + 8) * RS + wcol] = h2bits(l23);
                }
            }
            CP_WAIT0();
        } else {
            // fused head: o[t] += relu(v) . W3
#pragma unroll
            for (int mf = 0; mf < 2; mf++) {
#pragma unroll
                for (int nf = 0; nf < 8; nf++) {
                    const int h = nb + nf * 8 + 2 * (lane & 3);
                    float2 bb = *(const float2*)(bias_s + 256 + h);
                    float2 w3v = *(const float2*)(w3_s + h);
                    float v0 = fmaxf(acc[mf][nf][0] + bb.x, 0.f);
                    float v1 = fmaxf(acc[mf][nf][1] + bb.y, 0.f);
                    float v2 = fmaxf(acc[mf][nf][2] + bb.x, 0.f);
                    float v3 = fmaxf(acc[mf][nf][3] + bb.y, 0.f);
                    acc3[mf * 2 + 0] += v0 * w3v.x + v1 * w3v.y;
                    acc3[mf * 2 + 1] += v2 * w3v.x + v3 * w3v.y;
                }
            }
        }
        __syncthreads();
    }

    // reduce head over quad (lanes sharing the same t-row), then across h-warps
#pragma unroll
    for (int s = 0; s < 4; s++) {
        acc3[s] += __shfl_xor_sync(0xffffffffu, acc3[s], 1);
        acc3[s] += __shfl_xor_sync(0xffffffffu, acc3[s], 2);
    }
    if ((lane & 3) == 0) {
#pragma unroll
        for (int s = 0; s < 4; s++) {
            int r = mb + (s >> 1) * 16 + (lane >> 2) + (s & 1) * 8;
            atomicAdd(scr + r, acc3[s]);
        }
    }
    __syncthreads();

    if (tid < 128) {
        float o = scr[tid] + __ldg(b3g + j);
        float w = __ldg(ps + ((size_t)b * NJ + j) * NT + t0 + tid);
        atomicAdd(out + (size_t)b * NT + t0 + tid, o * w * (1.0f / 14.0f));
    }
}

extern "C" void kernel_launch(void* const* d_in, const int* in_sizes, int n_in,
                              void* d_out, int out_size) {
    (void)in_sizes; (void)n_in;
    const float* p  = (const float*)d_in[0];
    // d_in[1] = z (unused by the reference)
    const float* c  = (const float*)d_in[2];
    const float* ps = (const float*)d_in[3];
    const float* W0 = (const float*)d_in[4];
    const float* b0 = (const float*)d_in[5];
    const float* W1 = (const float*)d_in[6];
    const float* b1 = (const float*)d_in[7];
    const float* W2 = (const float*)d_in[8];
    const float* b2 = (const float*)d_in[9];
    const float* W3 = (const float*)d_in[10];
    const float* b3 = (const float*)d_in[11];
    float* out = (float*)d_out;

    cudaMemsetAsync(out, 0, (size_t)out_size * sizeof(float));

    convert_weights<<<dim3(NJ, 3), 256>>>(W0, W1, W2);

    cudaFuncSetAttribute(ptf_hmma, cudaFuncAttributeMaxDynamicSharedMemorySize,
                         SMEM_BYTES);
    dim3 grid(NT / 128, NB, NJ);   // 256 x 2 x 14, j slowest -> weight reuse in L2
    ptf_hmma<<<grid, 256, SMEM_BYTES>>>(p, c, ps, W0, b0, b1, b2, W3, b3, out);
}

// round 5
// speedup vs baseline: 5.9045x; 1.1911x over previous
#include <cuda_runtime.h>
#include <cuda_fp16.h>
#include <cstdint>

#define NJ 14
#define NB 2
#define NT 32768
#define NH 128
#define CIN 131

#define RS 68                // row stride in u32 (272 B): 16B-aligned, ldmatrix conflict-free
#define AH_W 0               // AH[256][RS]  (words)
#define WB_W 17408           // W[128][RS]   (words)
#define SM_WB_BYTES 69632
#define BIAS_W 26112         // 3*128 f
#define W0P_W  26496         // 3*128 f
#define W3_W   26880         // 128 f
#define SCR_W  27008         // 256 f
#define SMEM_BYTES 109056

__device__ uint32_t g_w16[NJ * 3 * 8192];   // fp16x2 weights [j][layer][h(128)][kw(64)]

// ---------- helpers ----------
__device__ __forceinline__ uint32_t smem_u32(const void* p) {
    uint32_t a;
    asm("{ .reg .u64 t; cvta.to.shared.u64 t, %1; cvt.u32.u64 %0, t; }" : "=r"(a) : "l"(p));
    return a;
}
__device__ __forceinline__ void ldsm4(uint32_t* r, uint32_t addr) {
    asm volatile("ldmatrix.sync.aligned.m8n8.x4.shared.b16 {%0,%1,%2,%3}, [%4];"
                 : "=r"(r[0]), "=r"(r[1]), "=r"(r[2]), "=r"(r[3]) : "r"(addr));
}
__device__ __forceinline__ void mma16816(float* d, const uint32_t* a,
                                         uint32_t b0, uint32_t b1) {
    asm volatile(
        "mma.sync.aligned.m16n8k16.row.col.f32.f16.f16.f32 "
        "{%0,%1,%2,%3}, {%4,%5,%6,%7}, {%8,%9}, {%0,%1,%2,%3};"
        : "+f"(d[0]), "+f"(d[1]), "+f"(d[2]), "+f"(d[3])
        : "r"(a[0]), "r"(a[1]), "r"(a[2]), "r"(a[3]), "r"(b0), "r"(b1));
}
__device__ __forceinline__ void cpasync16(uint32_t dst, const void* src) {
    asm volatile("cp.async.ca.shared.global [%0], [%1], 16;" :: "r"(dst), "l"(src));
}
#define CP_COMMIT() asm volatile("cp.async.commit_group;" ::: "memory")
#define CP_WAIT0()  asm volatile("cp.async.wait_group 0;" ::: "memory")

__device__ __forceinline__ uint32_t h2bits(half2 h) {
    return *reinterpret_cast<uint32_t*>(&h);
}

// ---------- weight pre-conversion (fp32 -> fp16 pairs along k) ----------
__global__ void convert_weights(const float* __restrict__ W0,
                                const float* __restrict__ W1,
                                const float* __restrict__ W2) {
    int j = blockIdx.x, l = blockIdx.y;
    const float* W = (l == 0) ? W0 : ((l == 1) ? W1 : W2);
    int K = (l == 0) ? CIN : NH;
    int koff = (l == 0) ? 3 : 0;
    uint32_t* dst = g_w16 + (size_t)(j * 3 + l) * 8192;
    for (int i = threadIdx.x; i < 8192; i += blockDim.x) {
        int h = i >> 6, kw = i & 63;
        const float* row = W + ((size_t)j * NH + h) * K + koff;
        half2 pk = __floats2half2_rn(row[2 * kw], row[2 * kw + 1]);
        dst[i] = h2bits(pk);
    }
}

// ---------- main kernel ----------
__global__ __launch_bounds__(256, 1)
void ptf_hmma(const float* __restrict__ p,
              const float* __restrict__ c,
              const float* __restrict__ ps,
              const float* __restrict__ W0g,
              const float* __restrict__ b0g,
              const float* __restrict__ b1g,
              const float* __restrict__ b2g,
              const float* __restrict__ W3g,
              const float* __restrict__ b3g,
              float* __restrict__ out) {
    extern __shared__ uint32_t sm[];
    uint32_t* AH = sm;                       // [256][RS]
    float* bias_s = (float*)(sm + BIAS_W);   // [3][128]
    float* w0p_s  = (float*)(sm + W0P_W);    // [3][128]
    float* w3_s   = (float*)(sm + W3_W);     // [128]
    float* scr    = (float*)(sm + SCR_W);    // [256]

    const int tid = threadIdx.x, lane = tid & 31, wid = tid >> 5;
    const int mb = (wid & 3) * 64;        // t-rows strip of this warp (64 rows)
    const int nb = (wid >> 2) * 64;       // h-cols strip (64 cols)
    const int t0 = blockIdx.x * 256, b = blockIdx.y, j = blockIdx.z;

    const uint32_t sbase = smem_u32(sm);
    // ldmatrix lane address components (validated in R4)
    const int arow_l = (lane & 7) + ((lane >> 3) & 1) * 8;
    const int akoff  = ((lane >> 4) & 1) * 16;
    const int brow_l = (lane & 7) + ((lane >> 4) & 1) * 8;
    const int bkoff  = ((lane >> 3) & 1) * 16;

    uint32_t aoff[4];
#pragma unroll
    for (int mf = 0; mf < 4; mf++)
        aoff[mf] = sbase + (uint32_t)((mb + mf * 16 + arow_l) * (RS * 4) + akoff);
    uint32_t boff[4];
#pragma unroll
    for (int nfp = 0; nfp < 4; nfp++)
        boff[nfp] = sbase + (uint32_t)(SM_WB_BYTES + (nb + nfp * 16 + brow_l) * (RS * 4) + bkoff);

    // ---- stage c -> AH (fp16 pairs along k), float4 coalesced reads ----
    {
        const float* cb = c + (size_t)b * NH * NT + t0;
#pragma unroll 2
        for (int i = tid; i < 4096; i += 256) {
            int tq = (i & 63) * 4;   // t quad
            int kw = i >> 6;         // 0..63
            float4 v0 = *(const float4*)(cb + (size_t)(2 * kw) * NT + tq);
            float4 v1 = *(const float4*)(cb + (size_t)(2 * kw + 1) * NT + tq);
            AH[(tq + 0) * RS + kw] = h2bits(__floats2half2_rn(v0.x, v1.x));
            AH[(tq + 1) * RS + kw] = h2bits(__floats2half2_rn(v0.y, v1.y));
            AH[(tq + 2) * RS + kw] = h2bits(__floats2half2_rn(v0.z, v1.z));
            AH[(tq + 3) * RS + kw] = h2bits(__floats2half2_rn(v0.w, v1.w));
        }
    }
    // ---- stage W0 via cp.async ----
    {
        const uint32_t* src = g_w16 + (size_t)(j * 3) * 8192;
        for (int i = tid; i < 2048; i += 256)
            cpasync16(sbase + SM_WB_BYTES + (i >> 4) * (RS * 4) + (i & 15) * 16, src + i * 4);
        CP_COMMIT();
    }
    if (tid < 128) {
        bias_s[tid]       = __ldg(b0g + j * NH + tid);
        bias_s[128 + tid] = __ldg(b1g + j * NH + tid);
        bias_s[256 + tid] = __ldg(b2g + j * NH + tid);
        const float* w0r = W0g + ((size_t)j * NH + tid) * CIN;
        w0p_s[tid]       = __ldg(w0r);
        w0p_s[128 + tid] = __ldg(w0r + 1);
        w0p_s[256 + tid] = __ldg(w0r + 2);
        w3_s[tid] = __ldg(W3g + j * NH + tid);
    }
    scr[tid] = 0.f;
    CP_WAIT0();
    __syncthreads();

    float acc3[8];
#pragma unroll
    for (int s = 0; s < 8; s++) acc3[s] = 0.f;

    for (int l = 0; l < 3; l++) {
        float acc[4][8][4];
#pragma unroll
        for (int mf = 0; mf < 4; mf++)
#pragma unroll
            for (int nf = 0; nf < 8; nf++)
#pragma unroll
                for (int q = 0; q < 4; q++) acc[mf][nf][q] = 0.f;

        // ---- k-loop: 8 chunks of k=16 ----
#pragma unroll
        for (int kc = 0; kc < 8; kc++) {
            uint32_t a[4][4];
#pragma unroll
            for (int mf = 0; mf < 4; mf++)
                ldsm4(a[mf], aoff[mf] + kc * 32);
#pragma unroll
            for (int nfp = 0; nfp < 4; nfp++) {
                uint32_t bw[4];
                ldsm4(bw, boff[nfp] + kc * 32);
#pragma unroll
                for (int mf = 0; mf < 4; mf++) {
                    mma16816(acc[mf][2 * nfp],     a[mf], bw[0], bw[1]);
                    mma16816(acc[mf][2 * nfp + 1], a[mf], bw[2], bw[3]);
                }
            }
        }
        __syncthreads();   // all reads of AH + W done

        if (l < 2) {
            // prefetch next layer's weights (overlaps with epilogue)
            const uint32_t* src = g_w16 + (size_t)(j * 3 + l + 1) * 8192;
            for (int i = tid; i < 2048; i += 256)
                cpasync16(sbase + SM_WB_BYTES + (i >> 4) * (RS * 4) + (i & 15) * 16, src + i * 4);
            CP_COMMIT();

            // epilogue: bias (+ p rank-3 for l==0), relu, pack fp16, in-place store
            float pva[4][3], pvb[4][3];
            if (l == 0) {
#pragma unroll
                for (int mf = 0; mf < 4; mf++) {
                    int r0 = t0 + mb + mf * 16 + (lane >> 2);
#pragma unroll
                    for (int d = 0; d < 3; d++) {
                        const float* pp = p + ((size_t)b * NJ * 3 + j * 3 + d) * NT;
                        pva[mf][d] = __ldg(pp + r0);
                        pvb[mf][d] = __ldg(pp + r0 + 8);
                    }
                }
            }
#pragma unroll
            for (int mf = 0; mf < 4; mf++) {
                const int r0 = mb + mf * 16 + (lane >> 2);
#pragma unroll
                for (int nf = 0; nf < 8; nf++) {
                    const int h = nb + nf * 8 + 2 * (lane & 3);
                    float2 bb = *(const float2*)(bias_s + l * 128 + h);
                    float v0 = acc[mf][nf][0] + bb.x;
                    float v1 = acc[mf][nf][1] + bb.y;
                    float v2 = acc[mf][nf][2] + bb.x;
                    float v3 = acc[mf][nf][3] + bb.y;
                    if (l == 0) {
#pragma unroll
                        for (int d = 0; d < 3; d++) {
                            float2 w = *(const float2*)(w0p_s + d * 128 + h);
                            v0 = fmaf(pva[mf][d], w.x, v0);
                            v1 = fmaf(pva[mf][d], w.y, v1);
                            v2 = fmaf(pvb[mf][d], w.x, v2);
                            v3 = fmaf(pvb[mf][d], w.y, v3);
                        }
                    }
                    v0 = fmaxf(v0, 0.f); v1 = fmaxf(v1, 0.f);
                    v2 = fmaxf(v2, 0.f); v3 = fmaxf(v3, 0.f);
                    const int wcol = h >> 1;
                    AH[r0 * RS + wcol]       = h2bits(__floats2half2_rn(v0, v1));
                    AH[(r0 + 8) * RS + wcol] = h2bits(__floats2half2_rn(v2, v3));
                }
            }
            CP_WAIT0();
        } else {
            // fused head: o[t] += relu(v) . W3
#pragma unroll
            for (int mf = 0; mf < 4; mf++) {
#pragma unroll
                for (int nf = 0; nf < 8; nf++) {
                    const int h = nb + nf * 8 + 2 * (lane & 3);
                    float2 bb = *(const float2*)(bias_s + 256 + h);
                    float2 w3v = *(const float2*)(w3_s + h);
                    float v0 = fmaxf(acc[mf][nf][0] + bb.x, 0.f);
                    float v1 = fmaxf(acc[mf][nf][1] + bb.y, 0.f);
                    float v2 = fmaxf(acc[mf][nf][2] + bb.x, 0.f);
                    float v3 = fmaxf(acc[mf][nf][3] + bb.y, 0.f);
                    acc3[mf * 2 + 0] += v0 * w3v.x + v1 * w3v.y;
                    acc3[mf * 2 + 1] += v2 * w3v.x + v3 * w3v.y;
                }
            }
        }
        __syncthreads();
    }

    // reduce head over quad (lanes sharing the same t-row), then across the 2 h-warps
#pragma unroll
    for (int s = 0; s < 8; s++) {
        acc3[s] += __shfl_xor_sync(0xffffffffu, acc3[s], 1);
        acc3[s] += __shfl_xor_sync(0xffffffffu, acc3[s], 2);
    }
    if ((lane & 3) == 0) {
#pragma unroll
        for (int s = 0; s < 8; s++) {
            int r = mb + (s >> 1) * 16 + (lane >> 2) + (s & 1) * 8;
            atomicAdd(scr + r, acc3[s]);
        }
    }
    __syncthreads();

    {
        float o = scr[tid] + __ldg(b3g + j);
        float w = __ldg(ps + ((size_t)b * NJ + j) * NT + t0 + tid);
        atomicAdd(out + (size_t)b * NT + t0 + tid, o * w * (1.0f / 14.0f));
    }
}

extern "C" void kernel_launch(void* const* d_in, const int* in_sizes, int n_in,
                              void* d_out, int out_size) {
    (void)in_sizes; (void)n_in;
    const float* p  = (const float*)d_in[0];
    // d_in[1] = z (unused by the reference)
    const float* c  = (const float*)d_in[2];
    const float* ps = (const float*)d_in[3];
    const float* W0 = (const float*)d_in[4];
    const float* b0 = (const float*)d_in[5];
    const float* W1 = (const float*)d_in[6];
    const float* b1 = (const float*)d_in[7];
    const float* W2 = (const float*)d_in[8];
    const float* b2 = (const float*)d_in[9];
    const float* W3 = (const float*)d_in[10];
    const float* b3 = (const float*)d_in[11];
    float* out = (float*)d_out;

    cudaMemsetAsync(out, 0, (size_t)out_size * sizeof(float));

    convert_weights<<<dim3(NJ, 3), 256>>>(W0, W1, W2);

    cudaFuncSetAttribute(ptf_hmma, cudaFuncAttributeMaxDynamicSharedMemorySize,
                         SMEM_BYTES);
    dim3 grid(NT / 256, NB, NJ);   // 128 x 2 x 14, j slowest -> weight reuse in L2
    ptf_hmma<<<grid, 256, SMEM_BYTES>>>(p, c, ps, W0, b0, b1, b2, W3, b3, out);
}

// round 6
// speedup vs baseline: 8.8513x; 1.4991x over previous
#include <cuda_runtime.h>
#include <cuda_fp16.h>
#include <cstdint>

#define NJ 14
#define NB 2
#define NT 32768
#define NH 128
#define CIN 131

#define RS 68                 // AH row stride in u32 (272 B): 16B-aligned, ldmatrix conflict-free
#define SM_WB_BYTES 34816     // W buffer starts after AH[128][RS]
#define BIAS_W 17408          // word offsets
#define W0P_W  17792
#define W3_W   18176
#define SCR_W  18304
#define SMEM_BYTES 74240      // 18560 words

__device__ uint32_t g_w16[NJ * 3 * 8192];          // fp16x2 weights [j][l][h(128)][kw(64)]
__device__ uint32_t g_c16[NB * 256 * 128 * 64];    // fp16x2 c tiles [b][tile][t(128)][kw(64)]

// ---------- helpers ----------
__device__ __forceinline__ uint32_t smem_u32(const void* p) {
    uint32_t a;
    asm("{ .reg .u64 t; cvta.to.shared.u64 t, %1; cvt.u32.u64 %0, t; }" : "=r"(a) : "l"(p));
    return a;
}
__device__ __forceinline__ void ldsm4(uint32_t* r, uint32_t addr) {
    asm volatile("ldmatrix.sync.aligned.m8n8.x4.shared.b16 {%0,%1,%2,%3}, [%4];"
                 : "=r"(r[0]), "=r"(r[1]), "=r"(r[2]), "=r"(r[3]) : "r"(addr));
}
__device__ __forceinline__ void mma16816(float* d, const uint32_t* a,
                                         uint32_t b0, uint32_t b1) {
    asm volatile(
        "mma.sync.aligned.m16n8k16.row.col.f32.f16.f16.f32 "
        "{%0,%1,%2,%3}, {%4,%5,%6,%7}, {%8,%9}, {%0,%1,%2,%3};"
        : "+f"(d[0]), "+f"(d[1]), "+f"(d[2]), "+f"(d[3])
        : "r"(a[0]), "r"(a[1]), "r"(a[2]), "r"(a[3]), "r"(b0), "r"(b1));
}
__device__ __forceinline__ void cpasync16(uint32_t dst, const void* src) {
    asm volatile("cp.async.ca.shared.global [%0], [%1], 16;" :: "r"(dst), "l"(src));
}
#define CP_COMMIT() asm volatile("cp.async.commit_group;" ::: "memory")
#define CP_WAIT0()  asm volatile("cp.async.wait_group 0;" ::: "memory")

__device__ __forceinline__ uint32_t h2bits(half2 h) {
    return *reinterpret_cast<uint32_t*>(&h);
}

// ---------- pre-kernels ----------
__global__ void convert_weights(const float* __restrict__ W0,
                                const float* __restrict__ W1,
                                const float* __restrict__ W2) {
    int j = blockIdx.x, l = blockIdx.y;
    const float* W = (l == 0) ? W0 : ((l == 1) ? W1 : W2);
    int K = (l == 0) ? CIN : NH;
    int koff = (l == 0) ? 3 : 0;
    uint32_t* dst = g_w16 + (size_t)(j * 3 + l) * 8192;
    for (int i = threadIdx.x; i < 8192; i += blockDim.x) {
        int h = i >> 6, kw = i & 63;
        const float* row = W + ((size_t)j * NH + h) * K + koff;
        dst[i] = h2bits(__floats2half2_rn(row[2 * kw], row[2 * kw + 1]));
    }
}

// c fp32 [b][ch][t] -> fp16x2 tiles [b][tile][t(128)][kw(64)], smem transpose
__global__ void convert_c(const float* __restrict__ c) {
    __shared__ uint32_t s[128 * 65];
    int tile = blockIdx.x, b = blockIdx.y;
    const float* cb = c + (size_t)b * NH * NT + tile * 128;
    uint32_t* dst = g_c16 + ((size_t)b * 256 + tile) * 8192;
    for (int i = threadIdx.x; i < 8192; i += 256) {
        int t = i & 127, kw = i >> 7;
        float v0 = __ldg(cb + (size_t)(2 * kw) * NT + t);
        float v1 = __ldg(cb + (size_t)(2 * kw + 1) * NT + t);
        s[t * 65 + kw] = h2bits(__floats2half2_rn(v0, v1));
    }
    __syncthreads();
    for (int i = threadIdx.x; i < 8192; i += 256)
        dst[i] = s[(i >> 6) * 65 + (i & 63)];
}

// ---------- main kernel ----------
__global__ __launch_bounds__(128, 2)
void ptf_hmma(const float* __restrict__ p,
              const float* __restrict__ ps,
              const float* __restrict__ W0g,
              const float* __restrict__ b0g,
              const float* __restrict__ b1g,
              const float* __restrict__ b2g,
              const float* __restrict__ W3g,
              const float* __restrict__ b3g,
              float* __restrict__ out) {
    extern __shared__ uint32_t sm[];
    uint32_t* AH = sm;                       // [128][RS]
    float* bias_s = (float*)(sm + BIAS_W);   // [3][128]
    float* w0p_s  = (float*)(sm + W0P_W);    // [3][128]
    float* w3_s   = (float*)(sm + W3_W);     // [128]
    float* scr    = (float*)(sm + SCR_W);    // [128]

    const int tid = threadIdx.x, lane = tid & 31, wid = tid >> 5;
    const int mb = (wid & 1) * 64;        // t strip (64 rows)
    const int nb = (wid >> 1) * 64;       // h strip (64 cols)
    const int t0 = blockIdx.x * 128, b = blockIdx.y, j = blockIdx.z;

    const uint32_t sbase = smem_u32(sm);
    const int arow_l = (lane & 7) + ((lane >> 3) & 1) * 8;
    const int akoff  = ((lane >> 4) & 1) * 16;
    const int brow_l = (lane & 7) + ((lane >> 4) & 1) * 8;
    const int bkoff  = ((lane >> 3) & 1) * 16;

    uint32_t aoff[4];
#pragma unroll
    for (int mf = 0; mf < 4; mf++)
        aoff[mf] = sbase + (uint32_t)((mb + mf * 16 + arow_l) * (RS * 4) + akoff);
    uint32_t boff[4];
#pragma unroll
    for (int nfp = 0; nfp < 4; nfp++)
        boff[nfp] = sbase + (uint32_t)(SM_WB_BYTES + (nb + nfp * 16 + brow_l) * (RS * 4) + bkoff);

    // ---- stage c tile (pre-converted) + W0 via cp.async, one group ----
    {
        const uint32_t* csrc = g_c16 + ((size_t)b * 256 + blockIdx.x) * 8192;
        for (int i = tid; i < 2048; i += 128)
            cpasync16(sbase + (i >> 4) * (RS * 4) + (i & 15) * 16, csrc + i * 4);
        const uint32_t* wsrc = g_w16 + (size_t)(j * 3) * 8192;
        for (int i = tid; i < 2048; i += 128)
            cpasync16(sbase + SM_WB_BYTES + (i >> 4) * (RS * 4) + (i & 15) * 16, wsrc + i * 4);
        CP_COMMIT();
    }
    {
        bias_s[tid]       = __ldg(b0g + j * NH + tid);
        bias_s[128 + tid] = __ldg(b1g + j * NH + tid);
        bias_s[256 + tid] = __ldg(b2g + j * NH + tid);
        const float* w0r = W0g + ((size_t)j * NH + tid) * CIN;
        w0p_s[tid]       = __ldg(w0r);
        w0p_s[128 + tid] = __ldg(w0r + 1);
        w0p_s[256 + tid] = __ldg(w0r + 2);
        w3_s[tid] = __ldg(W3g + j * NH + tid);
        scr[tid] = 0.f;
    }
    CP_WAIT0();
    __syncthreads();

    float acc3[8];
#pragma unroll
    for (int s = 0; s < 8; s++) acc3[s] = 0.f;

    for (int l = 0; l < 3; l++) {
        float acc[4][8][4];
#pragma unroll
        for (int mf = 0; mf < 4; mf++)
#pragma unroll
            for (int nf = 0; nf < 8; nf++)
#pragma unroll
                for (int q = 0; q < 4; q++) acc[mf][nf][q] = 0.f;

#pragma unroll
        for (int kc = 0; kc < 8; kc++) {
            uint32_t a[4][4];
#pragma unroll
            for (int mf = 0; mf < 4; mf++)
                ldsm4(a[mf], aoff[mf] + kc * 32);
#pragma unroll
            for (int nfp = 0; nfp < 4; nfp++) {
                uint32_t bw[4];
                ldsm4(bw, boff[nfp] + kc * 32);
#pragma unroll
                for (int mf = 0; mf < 4; mf++) {
                    mma16816(acc[mf][2 * nfp],     a[mf], bw[0], bw[1]);
                    mma16816(acc[mf][2 * nfp + 1], a[mf], bw[2], bw[3]);
                }
            }
        }
        __syncthreads();

        if (l < 2) {
            const uint32_t* src = g_w16 + (size_t)(j * 3 + l + 1) * 8192;
            for (int i = tid; i < 2048; i += 128)
                cpasync16(sbase + SM_WB_BYTES + (i >> 4) * (RS * 4) + (i & 15) * 16, src + i * 4);
            CP_COMMIT();

            float pva[4][3], pvb[4][3];
            if (l == 0) {
#pragma unroll
                for (int mf = 0; mf < 4; mf++) {
                    int r0 = t0 + mb + mf * 16 + (lane >> 2);
#pragma unroll
                    for (int d = 0; d < 3; d++) {
                        const float* pp = p + ((size_t)b * NJ * 3 + j * 3 + d) * NT;
                        pva[mf][d] = __ldg(pp + r0);
                        pvb[mf][d] = __ldg(pp + r0 + 8);
                    }
                }
            }
#pragma unroll
            for (int mf = 0; mf < 4; mf++) {
                const int r0 = mb + mf * 16 + (lane >> 2);
#pragma unroll
                for (int nf = 0; nf < 8; nf++) {
                    const int h = nb + nf * 8 + 2 * (lane & 3);
                    float2 bb = *(const float2*)(bias_s + l * 128 + h);
                    float v0 = acc[mf][nf][0] + bb.x;
                    float v1 = acc[mf][nf][1] + bb.y;
                    float v2 = acc[mf][nf][2] + bb.x;
                    float v3 = acc[mf][nf][3] + bb.y;
                    if (l == 0) {
#pragma unroll
                        for (int d = 0; d < 3; d++) {
                            float2 w = *(const float2*)(w0p_s + d * 128 + h);
                            v0 = fmaf(pva[mf][d], w.x, v0);
                            v1 = fmaf(pva[mf][d], w.y, v1);
                            v2 = fmaf(pvb[mf][d], w.x, v2);
                            v3 = fmaf(pvb[mf][d], w.y, v3);
                        }
                    }
                    v0 = fmaxf(v0, 0.f); v1 = fmaxf(v1, 0.f);
                    v2 = fmaxf(v2, 0.f); v3 = fmaxf(v3, 0.f);
                    const int wcol = h >> 1;
                    AH[r0 * RS + wcol]       = h2bits(__floats2half2_rn(v0, v1));
                    AH[(r0 + 8) * RS + wcol] = h2bits(__floats2half2_rn(v2, v3));
                }
            }
            CP_WAIT0();
        } else {
            // fused head: o[t] += relu(v) . W3
#pragma unroll
            for (int mf = 0; mf < 4; mf++) {
#pragma unroll
                for (int nf = 0; nf < 8; nf++) {
                    const int h = nb + nf * 8 + 2 * (lane & 3);
                    float2 bb = *(const float2*)(bias_s + 256 + h);
                    float2 w3v = *(const float2*)(w3_s + h);
                    float v0 = fmaxf(acc[mf][nf][0] + bb.x, 0.f);
                    float v1 = fmaxf(acc[mf][nf][1] + bb.y, 0.f);
                    float v2 = fmaxf(acc[mf][nf][2] + bb.x, 0.f);
                    float v3 = fmaxf(acc[mf][nf][3] + bb.y, 0.f);
                    acc3[mf * 2 + 0] += v0 * w3v.x + v1 * w3v.y;
                    acc3[mf * 2 + 1] += v2 * w3v.x + v3 * w3v.y;
                }
            }
        }
        __syncthreads();
    }

    // head reduce: quad shuffle, then atomics into scr (2 h-warps per t-row)
#pragma unroll
    for (int s = 0; s < 8; s++) {
        acc3[s] += __shfl_xor_sync(0xffffffffu, acc3[s], 1);
        acc3[s] += __shfl_xor_sync(0xffffffffu, acc3[s], 2);
    }
    if ((lane & 3) == 0) {
#pragma unroll
        for (int s = 0; s < 8; s++) {
            int r = mb + (s >> 1) * 16 + (lane >> 2) + (s & 1) * 8;
            atomicAdd(scr + r, acc3[s]);
        }
    }
    __syncthreads();

    {
        float o = scr[tid] + __ldg(b3g + j);
        float w = __ldg(ps + ((size_t)b * NJ + j) * NT + t0 + tid);
        atomicAdd(out + (size_t)b * NT + t0 + tid, o * w * (1.0f / 14.0f));
    }
}

extern "C" void kernel_launch(void* const* d_in, const int* in_sizes, int n_in,
                              void* d_out, int out_size) {
    (void)in_sizes; (void)n_in;
    const float* p  = (const float*)d_in[0];
    // d_in[1] = z (unused by the reference)
    const float* c  = (const float*)d_in[2];
    const float* ps = (const float*)d_in[3];
    const float* W0 = (const float*)d_in[4];
    const float* b0 = (const float*)d_in[5];
    const float* W1 = (const float*)d_in[6];
    const float* b1 = (const float*)d_in[7];
    const float* W2 = (const float*)d_in[8];
    const float* b2 = (const float*)d_in[9];
    const float* W3 = (const float*)d_in[10];
    const float* b3 = (const float*)d_in[11];
    float* out = (float*)d_out;

    cudaMemsetAsync(out, 0, (size_t)out_size * sizeof(float));

    convert_weights<<<dim3(NJ, 3), 256>>>(W0, W1, W2);
    convert_c<<<dim3(NT / 128, NB), 256>>>(c);

    cudaFuncSetAttribute(ptf_hmma, cudaFuncAttributeMaxDynamicSharedMemorySize,
                         SMEM_BYTES);
    dim3 grid(NT / 128, NB, NJ);   // 256 x 2 x 14, j slowest -> weight reuse in L2
    ptf_hmma<<<grid, 128, SMEM_BYTES>>>(p, ps, W0, b0, b1, b2, W3, b3, out);
}